// round 1
// baseline (speedup 1.0000x reference)
#include <cuda_runtime.h>
#include <mma.h>

using namespace nvcuda;

// Problem constants (fixed by the dataset)
constexpr int kE = 32;     // experts
constexpr int kD = 2048;   // hidden
constexpr int kF = 768;    // intermediate
constexpr int kT = 2048;   // tokens (B*S)

constexpr int BM = 128;
constexpr int BN = 128;
constexpr int BK = 16;

// Scratch: gated activations for all experts, fp32. [E][T][F] = 201 MB.
__device__ float g_gated[(size_t)kE * kT * kF];

using FragA = wmma::fragment<wmma::matrix_a, 16, 16, 8, wmma::precision::tf32, wmma::row_major>;
using FragB = wmma::fragment<wmma::matrix_b, 16, 16, 8, wmma::precision::tf32, wmma::row_major>;
using FragC = wmma::fragment<wmma::accumulator, 16, 16, 8, float>;

// ---------------------------------------------------------------------------
// GEMM1: for expert e, compute gated[e][t][f] = up * silu(gate),
//   gate = X(T,D) @ Wgu[e](D, 0:F), up = X @ Wgu[e](D, F:2F)
// Grid: (T/128, F/128, E). Block: 512 threads = 16 warps (4x4 warp grid).
// Each warp owns a 32x32 tile of gate AND the matching 32x32 tile of up.
// ---------------------------------------------------------------------------
__global__ __launch_bounds__(512, 1)
void moe_gemm1(const float* __restrict__ X,     // [T][D]
               const float* __restrict__ W)     // [E][D][2F]
{
    __shared__ __align__(128) float As[BM][20];    // 128 x 16 (+pad)
    __shared__ __align__(128) float Bg[BK][132];   // 16 x 128 (+pad)  gate cols
    __shared__ __align__(128) float Bu[BK][132];   // 16 x 128 (+pad)  up cols

    const int m0 = blockIdx.x * BM;
    const int n0 = blockIdx.y * BN;
    const int e  = blockIdx.z;
    const float* We = W + (size_t)e * kD * (2 * kF);

    const int tid  = threadIdx.x;
    const int warp = tid >> 5;
    const int wm   = (warp >> 2) * 32;
    const int wn   = (warp & 3) * 32;

    // Load assignments: A tile 128x16 -> 4 floats/thread; each B tile 16x128 -> 4 floats/thread
    const int ar = tid >> 2;          // 0..127
    const int ac = (tid & 3) * 4;     // 0,4,8,12
    const int br = tid >> 5;          // 0..15
    const int bc = (tid & 31) * 4;    // 0..124

    FragC accg[2][2], accu[2][2];
#pragma unroll
    for (int i = 0; i < 2; i++)
#pragma unroll
        for (int j = 0; j < 2; j++) {
            wmma::fill_fragment(accg[i][j], 0.0f);
            wmma::fill_fragment(accu[i][j], 0.0f);
        }

    const float* aPtr  = X  + (size_t)(m0 + ar) * kD + ac;
    const float* bgPtr = We + (size_t)br * (2 * kF) + n0 + bc;
    const float* buPtr = bgPtr + kF;

    // Prefetch K-tile 0 into registers
    float4 aReg  = *(const float4*)aPtr;
    float4 bgReg = *(const float4*)bgPtr;
    float4 buReg = *(const float4*)buPtr;

    for (int k0 = 0; k0 < kD; k0 += BK) {
        *(float4*)&As[ar][ac] = aReg;
        *(float4*)&Bg[br][bc] = bgReg;
        *(float4*)&Bu[br][bc] = buReg;
        __syncthreads();

        const int kn = k0 + BK;
        if (kn < kD) {
            aReg  = *(const float4*)(aPtr + kn);
            bgReg = *(const float4*)(bgPtr + (size_t)kn * (2 * kF));
            buReg = *(const float4*)(buPtr + (size_t)kn * (2 * kF));
        }

#pragma unroll
        for (int kk = 0; kk < BK; kk += 8) {
            FragA a[2];
            FragB bg[2], bu[2];
#pragma unroll
            for (int i = 0; i < 2; i++) {
                wmma::load_matrix_sync(a[i], &As[wm + i * 16][kk], 20);
#pragma unroll
                for (int q = 0; q < a[i].num_elements; q++)
                    a[i].x[q] = wmma::__float_to_tf32(a[i].x[q]);
            }
#pragma unroll
            for (int j = 0; j < 2; j++) {
                wmma::load_matrix_sync(bg[j], &Bg[kk][wn + j * 16], 132);
                wmma::load_matrix_sync(bu[j], &Bu[kk][wn + j * 16], 132);
#pragma unroll
                for (int q = 0; q < bg[j].num_elements; q++) {
                    bg[j].x[q] = wmma::__float_to_tf32(bg[j].x[q]);
                    bu[j].x[q] = wmma::__float_to_tf32(bu[j].x[q]);
                }
            }
#pragma unroll
            for (int i = 0; i < 2; i++)
#pragma unroll
                for (int j = 0; j < 2; j++) {
                    wmma::mma_sync(accg[i][j], a[i], bg[j], accg[i][j]);
                    wmma::mma_sync(accu[i][j], a[i], bu[j], accu[i][j]);
                }
        }
        __syncthreads();
    }

    // Epilogue: gated = up * silu(gate). gate/up accumulators have identical
    // fragment layouts, so the elementwise combine needs no layout knowledge.
    float* Gp = g_gated + (size_t)e * kT * kF;
#pragma unroll
    for (int i = 0; i < 2; i++)
#pragma unroll
        for (int j = 0; j < 2; j++) {
#pragma unroll
            for (int q = 0; q < accg[i][j].num_elements; q++) {
                const float gt = accg[i][j].x[q];
                const float up = accu[i][j].x[q];
                const float s  = gt / (1.0f + __expf(-gt));
                accg[i][j].x[q] = up * s;
            }
            wmma::store_matrix_sync(
                Gp + (size_t)(m0 + wm + i * 16) * kF + (n0 + wn + j * 16),
                accg[i][j], kF, wmma::mem_row_major);
        }
}

// ---------------------------------------------------------------------------
// GEMM2: out[t][d] = sum_e w[t,e] * (gated[e][t][:] @ Wd[e][:, d])
// Routing weight folded into A-tile smem load (row index is known there),
// so accumulation over all 32 experts is one long K loop (K = 32*768).
// Grid: (T/128, D/128). Block: 512 threads.
// ---------------------------------------------------------------------------
__global__ __launch_bounds__(512, 1)
void moe_gemm2(const float* __restrict__ Wd,   // [E][F][D]
               const float* __restrict__ RW,   // [T][E]
               float* __restrict__ Out)        // [T][D]
{
    __shared__ __align__(128) float As[BM][20];
    __shared__ __align__(128) float Bs[BK][132];

    const int m0 = blockIdx.x * BM;
    const int n0 = blockIdx.y * BN;

    const int tid  = threadIdx.x;
    const int warp = tid >> 5;
    const int wm   = (warp >> 2) * 32;
    const int wn   = (warp & 3) * 32;

    const int ar = tid >> 2;
    const int ac = (tid & 3) * 4;
    const int br = tid >> 5;
    const int bc = (tid & 31) * 4;

    FragC acc[2][2];
#pragma unroll
    for (int i = 0; i < 2; i++)
#pragma unroll
        for (int j = 0; j < 2; j++)
            wmma::fill_fragment(acc[i][j], 0.0f);

    constexpr int KT = kE * kF;   // 24576
    const float* rwRow = RW + (size_t)(m0 + ar) * kE;

    // Prefetch kt = 0 (expert 0, kin 0)
    float  w    = rwRow[0];
    float4 aReg = *(const float4*)(g_gated + (size_t)(m0 + ar) * kF + ac);
    aReg.x *= w; aReg.y *= w; aReg.z *= w; aReg.w *= w;
    float4 bReg = *(const float4*)(Wd + (size_t)br * kD + n0 + bc);

    for (int kt = 0; kt < KT; kt += BK) {
        *(float4*)&As[ar][ac] = aReg;
        *(float4*)&Bs[br][bc] = bReg;
        __syncthreads();

        const int kn = kt + BK;
        if (kn < KT) {
            const int en  = kn / kF;             // 768 divides evenly into 16-steps
            const int kin = kn - en * kF;
            w    = rwRow[en];
            aReg = *(const float4*)(g_gated + ((size_t)en * kT + (m0 + ar)) * kF + kin + ac);
            aReg.x *= w; aReg.y *= w; aReg.z *= w; aReg.w *= w;
            bReg = *(const float4*)(Wd + ((size_t)en * kF + (kin + br)) * kD + n0 + bc);
        }

#pragma unroll
        for (int kk = 0; kk < BK; kk += 8) {
            FragA a[2];
            FragB b[2];
#pragma unroll
            for (int i = 0; i < 2; i++) {
                wmma::load_matrix_sync(a[i], &As[wm + i * 16][kk], 20);
#pragma unroll
                for (int q = 0; q < a[i].num_elements; q++)
                    a[i].x[q] = wmma::__float_to_tf32(a[i].x[q]);
            }
#pragma unroll
            for (int j = 0; j < 2; j++) {
                wmma::load_matrix_sync(b[j], &Bs[kk][wn + j * 16], 132);
#pragma unroll
                for (int q = 0; q < b[j].num_elements; q++)
                    b[j].x[q] = wmma::__float_to_tf32(b[j].x[q]);
            }
#pragma unroll
            for (int i = 0; i < 2; i++)
#pragma unroll
                for (int j = 0; j < 2; j++)
                    wmma::mma_sync(acc[i][j], a[i], b[j], acc[i][j]);
        }
        __syncthreads();
    }

#pragma unroll
    for (int i = 0; i < 2; i++)
#pragma unroll
        for (int j = 0; j < 2; j++)
            wmma::store_matrix_sync(
                Out + (size_t)(m0 + wm + i * 16) * kD + (n0 + wn + j * 16),
                acc[i][j], kD, wmma::mem_row_major);
}

// ---------------------------------------------------------------------------
// kernel_launch
// Inputs (metadata order):
//   0: hidden_states  fp32 [B,S,D] = [T,D]
//   1: routing_weights fp32 [T,E]
//   2: router_indices  int32 [T,TOPK]   (UNUSED by the reference)
//   3: gate_up_proj    fp32 [E,D,2F]
//   4: down_proj       fp32 [E,F,D]
// Output: fp32 [T,D]
// ---------------------------------------------------------------------------
extern "C" void kernel_launch(void* const* d_in, const int* in_sizes, int n_in,
                              void* d_out, int out_size)
{
    const float* X   = (const float*)d_in[0];
    const float* RW  = (const float*)d_in[1];
    const float* Wgu = (const float*)d_in[3];
    const float* Wdn = (const float*)d_in[4];
    float* Out = (float*)d_out;

    dim3 g1(kT / BM, kF / BN, kE);   // (16, 6, 32)
    moe_gemm1<<<g1, 512>>>(X, Wgu);

    dim3 g2(kT / BM, kD / BN);       // (16, 16)
    moe_gemm2<<<g2, 512>>>(Wdn, RW, Out);
}